// round 1
// baseline (speedup 1.0000x reference)
#include <cuda_runtime.h>
#include <math.h>

// Problem constants
#define S_LEN   4096
#define B_SZ    8
#define HID     768
#define HS_DIM  256   // HIDDEN/3
#define NFREQ   384   // HID/2
#define HS_NFREQ 128  // HS_DIM/2

// Scratch: hs_pe table, 4096 x 256 floats = 4 MB (L2-resident)
__device__ float g_hs_pe[S_LEN * HS_DIM];

// ---------------------------------------------------------------------------
// Accurate sincos for |ang| up to ~5000: 3-term Cody-Waite 2*pi reduction
// (FMA chain, single rounding per step) followed by MUFU sincos on |r|<=~pi.
// Phase error ~4e-7, value error ~1e-6 total. Matches jax f32 reference
// well inside the 1e-3 tolerance.
// ---------------------------------------------------------------------------
__device__ __forceinline__ void sincos_red(float ang, float* s, float* c) {
    const double TWO_PI_D = 6.283185307179586476925286766559;
    const float  P1 = 6.28125f;
    const float  P2 = (float)(TWO_PI_D - (double)6.28125f);
    const float  P3 = (float)(TWO_PI_D - (double)6.28125f - (double)((float)(TWO_PI_D - (double)6.28125f)));
    const float  INV2PI = 0.15915494309189535f;
    float k = rintf(ang * INV2PI);
    float r = fmaf(-k, P1, ang);
    r = fmaf(-k, P2, r);
    r = fmaf(-k, P3, r);
    __sincosf(r, s, c);
}

// ---------------------------------------------------------------------------
// Prologue: build hs_pe = sin_table(256)[:4096] (interleaved sin/cos pairs,
// i.e. row layout [sin f0, cos f0? no -> [0::2]=sin, [1::2]=cos] which is
// exactly (sin_k, cos_k) pairs). Each thread owns one frequency k and 16
// positions so expf(div) is hoisted 16x. float2 stores are coalesced.
// ---------------------------------------------------------------------------
__global__ __launch_bounds__(128) void hs_pe_kernel() {
    const int k  = threadIdx.x;          // 0..127 frequency
    const int p0 = blockIdx.x * 16;      // 256 blocks x 16 positions
    const float CEXP = (float)(-9.210340371976184 / 256.0); // -ln(1e4)/256
    float div = expf((float)(2 * k) * CEXP);
    float2* out = (float2*)g_hs_pe;
#pragma unroll
    for (int j = 0; j < 16; j++) {
        int p = p0 + j;
        float sv, cv;
        sincos_red((float)p * div, &sv, &cv);
        out[p * HS_NFREQ + k] = make_float2(sv, cv);
    }
}

// ---------------------------------------------------------------------------
// Main fused kernel: one CTA per sequence position s.
//   Phase 1: CTA computes pe[s][0:768] into SMEM (trig cost shared across
//            the 8 batch rows and hidden under the DRAM traffic).
//            Also stages type_emb (2 rows), ln_w, ln_b in SMEM.
//   Phase 2: warp w handles batch b=w: gathers word row (DRAM), hs_pe row
//            (L2), adds pe + type, LayerNorms in registers, streams out.
// ---------------------------------------------------------------------------
__global__ __launch_bounds__(256) void emb_ln_kernel(
    const int*   __restrict__ input_ids,     // [8,4096]
    const int*   __restrict__ tok_struct,    // [8,4096,3]
    const int*   __restrict__ token_type,    // [8,4096]
    const float* __restrict__ word_emb,      // [30522,768]
    const float* __restrict__ type_emb,      // [2,768]
    const float* __restrict__ ln_w,          // [768]
    const float* __restrict__ ln_b,          // [768]
    float*       __restrict__ out)           // [8,4096,768]
{
    __shared__ float s_pe[HID];
    __shared__ float s_type[2 * HID];
    __shared__ float s_w[HID];
    __shared__ float s_b[HID];

    const int s   = blockIdx.x;
    const int tid = threadIdx.x;

    // Phase 1: pe row (384 freq pairs over 256 threads)
    {
        const float CEXP = (float)(-9.210340371976184 / 768.0); // -ln(1e4)/768
        for (int k = tid; k < NFREQ; k += 256) {
            float div = expf((float)(2 * k) * CEXP);
            float sv, cv;
            sincos_red((float)s * div, &sv, &cv);
            s_pe[2 * k]     = sv;
            s_pe[2 * k + 1] = cv;
        }
        for (int i = tid; i < HID; i += 256) {
            s_type[i]       = type_emb[i];
            s_type[HID + i] = type_emb[HID + i];
            s_w[i] = ln_w[i];
            s_b[i] = ln_b[i];
        }
    }
    __syncthreads();

    // Phase 2: warp-per-(batch,row)
    const int warp = tid >> 5;
    const int lane = tid & 31;
    const int b    = warp;                       // 8 warps == 8 batches
    const int idx  = b * S_LEN + s;

    const int tok = input_ids[idx];
    const int tt  = token_type[idx];
    const int pp  = tok_struct[idx * 3];         // para_pos

    const float4* wrow  = (const float4*)(word_emb + (size_t)tok * HID);
    const float4* hrow  = (const float4*)(g_hs_pe + (size_t)pp * HS_DIM);
    const float4* perow = (const float4*)s_pe;
    const float4* trow  = (const float4*)(s_type + tt * HID);

    float4 v[6];
    float sum = 0.f, sumsq = 0.f;
#pragma unroll
    for (int i = 0; i < 6; i++) {
        const int c = lane + 32 * i;             // float4 chunk 0..191
        float4 w4 = wrow[c];
        float4 h4 = hrow[c & 63];                // struct = concat(g,g,g)
        float4 p4 = perow[c];
        float4 t4 = trow[c];
        float4 e;
        e.x = w4.x + h4.x + p4.x + t4.x;
        e.y = w4.y + h4.y + p4.y + t4.y;
        e.z = w4.z + h4.z + p4.z + t4.z;
        e.w = w4.w + h4.w + p4.w + t4.w;
        v[i] = e;
        sum   += (e.x + e.y) + (e.z + e.w);
        sumsq += (e.x * e.x + e.y * e.y) + (e.z * e.z + e.w * e.w);
    }

#pragma unroll
    for (int off = 16; off > 0; off >>= 1) {
        sum   += __shfl_xor_sync(0xFFFFFFFFu, sum,   off);
        sumsq += __shfl_xor_sync(0xFFFFFFFFu, sumsq, off);
    }

    const float inv_n = 1.0f / 768.0f;
    float mu   = sum * inv_n;
    float var  = fmaf(sumsq, inv_n, -mu * mu);
    var = var < 0.f ? 0.f : var;
    float rstd = rsqrtf(var + 1e-12f);

    float4* orow = (float4*)(out + (size_t)idx * HID);
#pragma unroll
    for (int i = 0; i < 6; i++) {
        const int c = lane + 32 * i;
        float4 e  = v[i];
        float4 wg = ((const float4*)s_w)[c];
        float4 bi = ((const float4*)s_b)[c];
        float4 o;
        o.x = fmaf((e.x - mu) * rstd, wg.x, bi.x);
        o.y = fmaf((e.y - mu) * rstd, wg.y, bi.y);
        o.z = fmaf((e.z - mu) * rstd, wg.z, bi.z);
        o.w = fmaf((e.w - mu) * rstd, wg.w, bi.w);
        __stcs(&orow[c], o);                     // streaming store: keep L2 for word_emb
    }
}

// ---------------------------------------------------------------------------
// Launch
// ---------------------------------------------------------------------------
extern "C" void kernel_launch(void* const* d_in, const int* in_sizes, int n_in,
                              void* d_out, int out_size) {
    const int*   input_ids  = (const int*)  d_in[0];
    const int*   tok_struct = (const int*)  d_in[1];
    // d_in[2] = sent_struct_vec (unused by the reference output)
    const int*   token_type = (const int*)  d_in[3];
    const float* word_emb   = (const float*)d_in[4];
    const float* type_emb   = (const float*)d_in[5];
    const float* ln_w       = (const float*)d_in[6];
    const float* ln_b       = (const float*)d_in[7];
    float*       out        = (float*)d_out;

    hs_pe_kernel<<<S_LEN / 16, 128>>>();
    emb_ln_kernel<<<S_LEN, 256>>>(input_ids, tok_struct, token_type,
                                  word_emb, type_emb, ln_w, ln_b, out);
}